// round 10
// baseline (speedup 1.0000x reference)
#include <cuda_runtime.h>
#include <cstdint>

// SheafConvLayer:
//   out[n,:] = relu( W_self[n] @ x[n] + b_self[n]
//                    + sum_{e: dst[e]==n} ( W_edge[e] @ x[src[e]] + b_edge[e] ) )
// D_IN = D_OUT = 16.
//
// Inputs (metadata order):
//   0: x           f32 [N,16]
//   1: edge_index  int [2,E]  (int32 or int64, runtime-detected)
//   2: weight_edge f32 [E,16,16]
//   3: weight_self f32 [N,16,16]
//   4: bias_edge   f32 [E,16]
//   5: bias_self   f32 [N,16]
// out: f32 [N,16]
//
// Strategy: the 819MB weight_edge stream was L1tex-wavefront-bound (per-thread
// 256B chunks -> 1 sector per line per LDG). Now: cp.async.cg stages tiles of
// 32 matrices (32KB) into SMEM with fully coalesced 16B/lane gmem reads and an
// XOR swizzle on the SMEM slot so the compute-side LDS.128 is conflict-free.
// 3-stage pipeline, persistent blocks, one red.add.v2 per (edge, row-pair).

#define D 16
#define TILE 32
#define STAGES 3
#define W_STAGE_BYTES (TILE * 1024)            // 32 KB
#define B_STAGE_BYTES (TILE * 64)              // 2 KB
#define SMEM_TOTAL (STAGES * (W_STAGE_BYTES + B_STAGE_BYTES))  // 104448

__device__ int g_idx_is64;

__device__ __forceinline__ float dot4(float4 a, float4 b) {
    return a.x * b.x + a.y * b.y + a.z * b.z + a.w * b.w;
}

__device__ __forceinline__ void red_add_v2(float* addr, float a, float b) {
    asm volatile("red.global.add.v2.f32 [%0], {%1, %2};"
                 :: "l"(addr), "f"(a), "f"(b) : "memory");
}

__device__ __forceinline__ uint32_t smem_u32(const void* p) {
    uint32_t a;
    asm("{ .reg .u64 t; cvta.to.shared.u64 t, %1; cvt.u32.u64 %0, t; }"
        : "=r"(a) : "l"(p));
    return a;
}

__device__ __forceinline__ void cp16(uint32_t dst, const void* src) {
    asm volatile("cp.async.cg.shared.global [%0], [%1], 16;"
                 :: "r"(dst), "l"(src) : "memory");
}

// ---------------------------------------------------------------------------
// dtype detection: int64 indices < 2^31 -> all odd 32-bit words zero.
// ---------------------------------------------------------------------------
__global__ void detect_kernel(const int* __restrict__ w)
{
    int i = threadIdx.x;
    int nz = 0;
    #pragma unroll
    for (int k = 0; k < 4; k++) nz |= w[2 * (i * 4 + k) + 1];
    int any = __syncthreads_or(nz != 0);
    if (i == 0) g_idx_is64 = (any == 0) ? 1 : 0;
}

__global__ void __launch_bounds__(256)
zero_kernel(float4* __restrict__ out, int total4)
{
    int t = blockIdx.x * blockDim.x + threadIdx.x;
    if (t < total4) out[t] = make_float4(0.f, 0.f, 0.f, 0.f);
}

__global__ void __launch_bounds__(256)
relu_kernel(float4* __restrict__ out, int total4)
{
    int t = blockIdx.x * blockDim.x + threadIdx.x;
    if (t >= total4) return;
    float4 v = out[t];
    v.x = v.x > 0.f ? v.x : 0.f;
    v.y = v.y > 0.f ? v.y : 0.f;
    v.z = v.z > 0.f ? v.z : 0.f;
    v.w = v.w > 0.f ? v.w : 0.f;
    out[t] = v;
}

// ---------------------------------------------------------------------------
// Unified per-matrix matvec + scatter-add.
//   is_edge=1: src/dst from edge_index, W/Bq indexed by edge.
//   is_edge=0: src = dst = item id (self term).
// 256 threads, 32 matrices per tile, 8 threads per matrix, thread owns
// rows 2h and 2h+1 (one contiguous 128B SMEM chunk).
// ---------------------------------------------------------------------------
__global__ void __launch_bounds__(256)
gemv_scatter_kernel(const float* __restrict__ x,
                    const void* __restrict__ edge_index,
                    const float* __restrict__ W,
                    const float* __restrict__ Bq,
                    float* __restrict__ out,
                    int count, int n_nodes, int is_edge, int n_tiles)
{
    extern __shared__ char smem[];
    float* sw = (float*)smem;                                   // weights stages
    float* sb = (float*)(smem + STAGES * W_STAGE_BYTES);        // bias stages

    const int t = threadIdx.x;
    const int e_loc = t >> 3;
    const int h = t & 7;

    // number of tiles this block owns (tile ids: blockIdx.x + i*gridDim.x)
    int n_local = 0;
    if ((int)blockIdx.x < n_tiles)
        n_local = (n_tiles - blockIdx.x + gridDim.x - 1) / gridDim.x;

    auto issue_stage = [&](int stage, int tile) {
        int rem = count - tile * TILE; if (rem > TILE) rem = TILE;
        // weights: rem*64 16B-units, coalesced gmem, swizzled smem slot j^h
        const char* wsrc = (const char*)W + (size_t)tile * W_STAGE_BYTES;
        char* wdst = smem + stage * W_STAGE_BYTES;
        int wunits = rem * 64;
        #pragma unroll
        for (int u = 0; u < 8; u++) {
            int m = t + u * 256;
            if (m < wunits) {
                int e  = m >> 6;
                int hh = (m >> 3) & 7;
                int j  = m & 7;
                uint32_t d = smem_u32(wdst + e * 1024 + hh * 128 + ((j ^ hh) << 4));
                cp16(d, wsrc + (size_t)m * 16);
            }
        }
        // bias: rem*4 16B-units, linear
        const char* bsrc = (const char*)Bq + (size_t)tile * B_STAGE_BYTES;
        char* bdst = smem + STAGES * W_STAGE_BYTES + stage * B_STAGE_BYTES;
        if (t < rem * 4) {
            uint32_t d = smem_u32(bdst + t * 16);
            cp16(d, bsrc + (size_t)t * 16);
        }
        asm volatile("cp.async.commit_group;" ::: "memory");
    };

    // prologue: stages 0..STAGES-2
    #pragma unroll
    for (int p = 0; p < STAGES - 1; p++) {
        if (p < n_local) issue_stage(p, blockIdx.x + p * gridDim.x);
        else asm volatile("cp.async.commit_group;" ::: "memory");
    }

    const int is64 = g_idx_is64;

    for (int i = 0; i < n_local; i++) {
        // issue tile i+STAGES-1 (or empty group to keep wait_group counting)
        int q = i + STAGES - 1;
        if (q < n_local) issue_stage(q % STAGES, blockIdx.x + q * gridDim.x);
        else asm volatile("cp.async.commit_group;" ::: "memory");

        asm volatile("cp.async.wait_group %0;" :: "n"(STAGES - 1) : "memory");
        __syncthreads();

        const int stage = i % STAGES;
        const int tile  = blockIdx.x + i * gridDim.x;
        int rem = count - tile * TILE; if (rem > TILE) rem = TILE;

        if (e_loc < rem) {
            long long g = (long long)tile * TILE + e_loc;
            long long src, dst;
            bool ok = true;
            if (is_edge) {
                if (is64) {
                    const long long* p = (const long long*)edge_index;
                    src = p[g];
                    dst = p[(size_t)count + g];
                } else {
                    const int* p = (const int*)edge_index;
                    src = p[g];
                    dst = p[(size_t)count + g];
                }
                ok = (src >= 0 && src < n_nodes && dst >= 0 && dst < n_nodes);
            } else {
                src = g; dst = g;
            }
            if (ok) {
                const float4* xp = (const float4*)(x + (size_t)src * D);
                float4 x0 = xp[0], x1 = xp[1], x2 = xp[2], x3 = xp[3];

                const float* wst = sw + (size_t)stage * (W_STAGE_BYTES / 4)
                                      + e_loc * 256 + h * 32;   // chunk base (floats)
                float2 b2 = *(const float2*)(sb + stage * (B_STAGE_BYTES / 4)
                                                + e_loc * 16 + h * 2);
                float a0 = b2.x, a1 = b2.y;
                float4 w;
                // slot k^h holds original column-group k (swizzle inverse)
                w = *(const float4*)(wst + ((0 ^ h) << 2)); a0 += dot4(w, x0);
                w = *(const float4*)(wst + ((1 ^ h) << 2)); a0 += dot4(w, x1);
                w = *(const float4*)(wst + ((2 ^ h) << 2)); a0 += dot4(w, x2);
                w = *(const float4*)(wst + ((3 ^ h) << 2)); a0 += dot4(w, x3);
                w = *(const float4*)(wst + ((4 ^ h) << 2)); a1 += dot4(w, x0);
                w = *(const float4*)(wst + ((5 ^ h) << 2)); a1 += dot4(w, x1);
                w = *(const float4*)(wst + ((6 ^ h) << 2)); a1 += dot4(w, x2);
                w = *(const float4*)(wst + ((7 ^ h) << 2)); a1 += dot4(w, x3);

                red_add_v2(out + (size_t)dst * D + h * 2, a0, a1);
            }
        }
        __syncthreads();   // all reads done before this stage is overwritten
    }
}

extern "C" void kernel_launch(void* const* d_in, const int* in_sizes, int n_in,
                              void* d_out, int out_size)
{
    const float* x      = (const float*)d_in[0];
    const void*  eidx   = d_in[1];
    const float* w_edge = (const float*)d_in[2];
    const float* w_self = (const float*)d_in[3];
    const float* b_edge = (const float*)d_in[4];
    const float* b_self = (const float*)d_in[5];
    float*       out    = (float*)d_out;

    int n_nodes = in_sizes[0] / D;
    int n_edges = in_sizes[2] / (D * D);

    // Unconditional (no static guards allowed): idempotent host-side attribute.
    cudaFuncSetAttribute(gemv_scatter_kernel,
                         cudaFuncAttributeMaxDynamicSharedMemorySize, SMEM_TOTAL);

    // 0) index dtype detection
    detect_kernel<<<1, 256>>>((const int*)eidx);

    // 1) zero output (both terms accumulate atomically)
    int total4 = (n_nodes * D) / 4;
    zero_kernel<<<(total4 + 255) / 256, 256>>>((float4*)out, total4);

    // 2) self term
    {
        int n_tiles = (n_nodes + TILE - 1) / TILE;
        int grid = n_tiles < 296 ? n_tiles : 296;
        gemv_scatter_kernel<<<grid, 256, SMEM_TOTAL>>>(
            x, eidx, w_self, b_self, out, n_nodes, n_nodes, 0, n_tiles);
    }

    // 3) edge term
    {
        int n_tiles = (n_edges + TILE - 1) / TILE;
        int grid = n_tiles < 296 ? n_tiles : 296;
        gemv_scatter_kernel<<<grid, 256, SMEM_TOTAL>>>(
            x, eidx, w_edge, b_edge, out, n_edges, n_nodes, 1, n_tiles);
    }

    // 4) relu
    relu_kernel<<<(total4 + 255) / 256, 256>>>((float4*)out, total4);
}

// round 11
// speedup vs baseline: 1.3685x; 1.3685x over previous
#include <cuda_runtime.h>
#include <cstdint>

// SheafConvLayer:
//   out[n,:] = relu( W_self[n] @ x[n] + b_self[n]
//                    + sum_{e: dst[e]==n} ( W_edge[e] @ x[src[e]] + b_edge[e] ) )
// D = 16.
//
// Inputs (metadata order):
//   0: x           f32 [N,16]
//   1: edge_index  int [2,E]  (int32 or int64, runtime-detected)
//   2: weight_edge f32 [E,16,16]
//   3: weight_self f32 [N,16,16]
//   4: bias_edge   f32 [E,16]
//   5: bias_self   f32 [N,16]
// out: f32 [N,16]
//
// R10 evidence: block-wide pipeline was latency-bound (occ 23.9%, DRAM 59%,
// nothing saturated). This version: per-WARP autonomous cp.async pipelines
// (no __syncthreads in the mainloop), 4 edges/warp-tile, 2 stages, 8.5KB/warp
// -> 68KB/CTA -> 3 CTAs/SM (24 warps). Edge indices + x[src] gathers are
// software-pipelined one tile ahead in registers.

#define D 16
#define EPW 4                       // edges per warp-tile
#define WT_W_BYTES (EPW * 1024)     // 4 KB weights per stage
#define WT_B_BYTES (EPW * 64)       // 256 B bias per stage
#define STAGE_BYTES (WT_W_BYTES + WT_B_BYTES)   // 4352 (multiple of 128)
#define NSTAGE 2
#define WARP_SMEM (NSTAGE * STAGE_BYTES)        // 8704
#define BLOCK_WARPS 8
#define SMEM_TOTAL (BLOCK_WARPS * WARP_SMEM)    // 69632

__device__ int g_idx_is64;

__device__ __forceinline__ float dot4(float4 a, float4 b) {
    return a.x * b.x + a.y * b.y + a.z * b.z + a.w * b.w;
}

__device__ __forceinline__ void red_add_v2(float* addr, float a, float b) {
    asm volatile("red.global.add.v2.f32 [%0], {%1, %2};"
                 :: "l"(addr), "f"(a), "f"(b) : "memory");
}

__device__ __forceinline__ uint32_t smem_u32(const void* p) {
    uint32_t a;
    asm("{ .reg .u64 t; cvta.to.shared.u64 t, %1; cvt.u32.u64 %0, t; }"
        : "=r"(a) : "l"(p));
    return a;
}

__device__ __forceinline__ void cp16(uint32_t dst, const void* src) {
    asm volatile("cp.async.cg.shared.global [%0], [%1], 16;"
                 :: "r"(dst), "l"(src) : "memory");
}

__device__ __forceinline__ void cp_commit() {
    asm volatile("cp.async.commit_group;" ::: "memory");
}

__device__ __forceinline__ void cp_wait1() {
    asm volatile("cp.async.wait_group 1;" ::: "memory");
}

// ---------------------------------------------------------------------------
// dtype detection: int64 indices < 2^31 -> all odd 32-bit words zero.
// ---------------------------------------------------------------------------
__global__ void detect_kernel(const int* __restrict__ w)
{
    int i = threadIdx.x;
    int nz = 0;
    #pragma unroll
    for (int k = 0; k < 4; k++) nz |= w[2 * (i * 4 + k) + 1];
    int any = __syncthreads_or(nz != 0);
    if (i == 0) g_idx_is64 = (any == 0) ? 1 : 0;
}

__global__ void __launch_bounds__(256)
zero_kernel(float4* __restrict__ out, int total4)
{
    int t = blockIdx.x * blockDim.x + threadIdx.x;
    if (t < total4) out[t] = make_float4(0.f, 0.f, 0.f, 0.f);
}

__global__ void __launch_bounds__(256)
relu_kernel(float4* __restrict__ out, int total4)
{
    int t = blockIdx.x * blockDim.x + threadIdx.x;
    if (t >= total4) return;
    float4 v = out[t];
    v.x = v.x > 0.f ? v.x : 0.f;
    v.y = v.y > 0.f ? v.y : 0.f;
    v.z = v.z > 0.f ? v.z : 0.f;
    v.w = v.w > 0.f ? v.w : 0.f;
    out[t] = v;
}

// ---------------------------------------------------------------------------
// Per-warp autonomous gemv + scatter-add. Warp-tile = 4 matrices; within the
// warp: lane -> (e_loc = lane>>3, h = lane&7), thread owns rows 2h,2h+1.
// Weights staged via cp.async with XOR-swizzled smem slots (conflict-free
// 8-lane LDS.128 phases). No block barriers anywhere in the loop.
// ---------------------------------------------------------------------------
__global__ void __launch_bounds__(256)
gemv_scatter_kernel(const float* __restrict__ x,
                    const void* __restrict__ edge_index,
                    const float* __restrict__ W,
                    const float* __restrict__ Bq,
                    float* __restrict__ out,
                    int count, int n_nodes, int is_edge)
{
    extern __shared__ char smem[];
    const int wid  = threadIdx.x >> 5;
    const int lane = threadIdx.x & 31;
    const int e_loc = lane >> 3;
    const int h     = lane & 7;
    char* wsm = smem + wid * WARP_SMEM;

    const int n_wtiles = (count + EPW - 1) / EPW;
    const int wslot    = blockIdx.x * BLOCK_WARPS + wid;
    const int wstride  = gridDim.x * BLOCK_WARPS;
    const int is64     = g_idx_is64;

    int n_local = (wslot < n_wtiles) ? (n_wtiles - wslot + wstride - 1) / wstride : 0;
    if (n_local == 0) return;

    auto issue_stage = [&](int buf, int i_local, bool real) {
        if (real) {
            long long ti = (long long)wslot + (long long)i_local * wstride;
            long long base_e = ti * EPW;
            int rem = (int)((count - base_e) < EPW ? (count - base_e) : EPW);
            const char* wsrc = (const char*)W + base_e * 1024;
            char* wd = wsm + buf * STAGE_BYTES;
            int units = rem * 64;
            #pragma unroll
            for (int u = 0; u < 8; u++) {
                int m = lane + u * 32;
                if (m < units) {
                    int e  = m >> 6;
                    int hh = (m >> 3) & 7;
                    int j  = m & 7;
                    cp16(smem_u32(wd + e * 1024 + hh * 128 + ((j ^ hh) << 4)),
                         wsrc + (size_t)m * 16);
                }
            }
            const char* bsrc = (const char*)Bq + base_e * 64;
            if (lane < rem * 4)
                cp16(smem_u32(wd + WT_W_BYTES + lane * 16), bsrc + (size_t)lane * 16);
        }
        cp_commit();
    };

    // meta + x gather for warp-tile i_local (into caller regs)
    auto load_meta = [&](int i_local, long long& src, long long& dst, bool& ok,
                         float4& x0, float4& x1, float4& x2, float4& x3) {
        long long g = ((long long)wslot + (long long)i_local * wstride) * EPW + e_loc;
        ok = (g < count);
        src = g; dst = g;
        if (ok && is_edge) {
            if (is64) {
                const long long* p = (const long long*)edge_index;
                src = p[g];
                dst = p[(size_t)count + g];
            } else {
                const int* p = (const int*)edge_index;
                src = p[g];
                dst = p[(size_t)count + g];
            }
            ok = (src >= 0 && src < n_nodes && dst >= 0 && dst < n_nodes);
        }
        if (ok) {
            const float4* xp = (const float4*)(x + (size_t)src * D);
            x0 = xp[0]; x1 = xp[1]; x2 = xp[2]; x3 = xp[3];
        }
    };

    // prologue: stages for local tiles 0 and 1; meta/x for tile 0
    issue_stage(0, 0, true);
    issue_stage(1, 1, 1 < n_local);

    long long src_c, dst_c; bool ok_c;
    float4 c0, c1, c2, c3;
    load_meta(0, src_c, dst_c, ok_c, c0, c1, c2, c3);

    for (int i = 0; i < n_local; i++) {
        // prefetch meta + x for tile i+1 (overlaps with this tile's wait+compute)
        long long src_n, dst_n; bool ok_n;
        float4 n0, n1, n2, n3;
        if (i + 1 < n_local)
            load_meta(i + 1, src_n, dst_n, ok_n, n0, n1, n2, n3);

        cp_wait1();          // stage i complete (per-warp group counting)
        __syncwarp();

        if (ok_c) {
            const float* wst = (const float*)(wsm + (i & 1) * STAGE_BYTES)
                             + e_loc * 256 + h * 32;
            float2 b2 = *(const float2*)((const float*)(wsm + (i & 1) * STAGE_BYTES + WT_W_BYTES)
                                         + e_loc * 16 + h * 2);
            float a0 = b2.x, a1 = b2.y;
            float4 w;
            w = *(const float4*)(wst + ((0 ^ h) << 2)); a0 += dot4(w, c0);
            w = *(const float4*)(wst + ((1 ^ h) << 2)); a0 += dot4(w, c1);
            w = *(const float4*)(wst + ((2 ^ h) << 2)); a0 += dot4(w, c2);
            w = *(const float4*)(wst + ((3 ^ h) << 2)); a0 += dot4(w, c3);
            w = *(const float4*)(wst + ((4 ^ h) << 2)); a1 += dot4(w, c0);
            w = *(const float4*)(wst + ((5 ^ h) << 2)); a1 += dot4(w, c1);
            w = *(const float4*)(wst + ((6 ^ h) << 2)); a1 += dot4(w, c2);
            w = *(const float4*)(wst + ((7 ^ h) << 2)); a1 += dot4(w, c3);
            red_add_v2(out + (size_t)dst_c * D + h * 2, a0, a1);
        }

        __syncwarp();
        // refill the buffer we just consumed with tile i+2 (issued after all
        // reads in program order -> no write-before-read hazard)
        issue_stage(i & 1, i + 2, (i + 2) < n_local);

        src_c = src_n; dst_c = dst_n; ok_c = ok_n;
        c0 = n0; c1 = n1; c2 = n2; c3 = n3;
    }
}

extern "C" void kernel_launch(void* const* d_in, const int* in_sizes, int n_in,
                              void* d_out, int out_size)
{
    const float* x      = (const float*)d_in[0];
    const void*  eidx   = d_in[1];
    const float* w_edge = (const float*)d_in[2];
    const float* w_self = (const float*)d_in[3];
    const float* b_edge = (const float*)d_in[4];
    const float* b_self = (const float*)d_in[5];
    float*       out    = (float*)d_out;

    int n_nodes = in_sizes[0] / D;
    int n_edges = in_sizes[2] / (D * D);

    cudaFuncSetAttribute(gemv_scatter_kernel,
                         cudaFuncAttributeMaxDynamicSharedMemorySize, SMEM_TOTAL);

    // 0) index dtype detection
    detect_kernel<<<1, 256>>>((const int*)eidx);

    // 1) zero output (both terms accumulate atomically)
    int total4 = (n_nodes * D) / 4;
    zero_kernel<<<(total4 + 255) / 256, 256>>>((float4*)out, total4);

    const int GRID = 444;   // 3 CTAs/SM x 148 SMs

    // 2) self term (src = dst = node id)
    gemv_scatter_kernel<<<GRID, 256, SMEM_TOTAL>>>(
        x, eidx, w_self, b_self, out, n_nodes, n_nodes, 0);

    // 3) edge term
    gemv_scatter_kernel<<<GRID, 256, SMEM_TOTAL>>>(
        x, eidx, w_edge, b_edge, out, n_edges, n_nodes, 1);

    // 4) relu
    relu_kernel<<<(total4 + 255) / 256, 256>>>((float4*)out, total4);
}